// round 1
// baseline (speedup 1.0000x reference)
#include <cuda_runtime.h>
#include <cuda_bf16.h>

// Problem shape (fixed by the reference setup_inputs)
#define BB 1024
#define MM 256
#define LL 256

// Scratch: sin/cos of x (B*M) and of phis (M*L). Static __device__ arrays
// (no allocation allowed in kernel_launch).
__device__ float g_sx[BB * MM];
__device__ float g_cx[BB * MM];
__device__ float g_sp[MM * LL];
__device__ float g_cp[MM * LL];

// Prep: compute sincos of x and phis. 262144 threads covers both arrays.
__global__ void prep_sincos_kernel(const float* __restrict__ x,
                                   const float* __restrict__ phis) {
    int i = blockIdx.x * blockDim.x + threadIdx.x;
    if (i < BB * MM) {
        float s, c;
        sincosf(x[i], &s, &c);
        g_sx[i] = s;
        g_cx[i] = c;
    }
    if (i < MM * LL) {
        float s, c;
        sincosf(phis[i], &s, &c);
        g_sp[i] = s;
        g_cp[i] = c;
    }
}

__device__ __forceinline__ float elem(float xv, float sx, float cx, float iv,
                                      float phv, float cpv, float spv) {
    float diff = xv - phv;                       // same fp32 op as reference
    bool mask = (diff > -iv) & (diff <= iv);     // exact reference semantics
    float cosd = fmaf(cx, cpv, sx * spv);        // cos(x - phi) via identity
    float val = fmaf(0.5f, cosd, 0.5f);
    return mask ? val : 0.0f;
}

// Main: one thread per output float4. out is (B, M*L) row-major =>
// linear index = b*65536 + m*256 + l. float4 index: 16,777,216 total.
__global__ void __launch_bounds__(256)
bcos_main_kernel(const float* __restrict__ x,
                 const float* __restrict__ phis,
                 const float* __restrict__ interval,
                 float4* __restrict__ out) {
    int idx = blockIdx.x * blockDim.x + threadIdx.x;  // float4 index
    int rem = idx & 16383;       // within one batch row (65536/4 float4s)
    int b   = idx >> 14;
    int m   = rem >> 6;          // 64 float4s per m-row (L=256)
    int ml4 = rem;               // == m*64 + l4, contiguous over phi tables
    int bm  = b * MM + m;

    float xv = __ldg(x + bm);
    float sx = g_sx[bm];
    float cx = g_cx[bm];
    float iv = __ldg(interval + m);

    float4 ph = reinterpret_cast<const float4*>(phis)[ml4];
    float4 cp = reinterpret_cast<const float4*>(g_cp)[ml4];
    float4 sp = reinterpret_cast<const float4*>(g_sp)[ml4];

    float4 o;
    o.x = elem(xv, sx, cx, iv, ph.x, cp.x, sp.x);
    o.y = elem(xv, sx, cx, iv, ph.y, cp.y, sp.y);
    o.z = elem(xv, sx, cx, iv, ph.z, cp.z, sp.z);
    o.w = elem(xv, sx, cx, iv, ph.w, cp.w, sp.w);

    out[idx] = o;
}

extern "C" void kernel_launch(void* const* d_in, const int* in_sizes, int n_in,
                              void* d_out, int out_size) {
    const float* x        = (const float*)d_in[0];  // (1024, 256)
    const float* phis     = (const float*)d_in[1];  // (256, 256)
    const float* interval = (const float*)d_in[2];  // (256,)
    float4* out = (float4*)d_out;                   // (1024, 65536) fp32

    // Prep sincos tables: 262144 threads
    prep_sincos_kernel<<<(BB * MM + 255) / 256, 256>>>(x, phis);

    // Main: 16,777,216 float4 threads
    int total4 = BB * MM * LL / 4;
    bcos_main_kernel<<<total4 / 256, 256>>>(x, phis, interval, out);
}

// round 3
// speedup vs baseline: 1.5846x; 1.5846x over previous
#include <cuda_runtime.h>
#include <cuda_bf16.h>

// Problem shape (fixed by the reference setup_inputs)
#define BB 1024
#define MM 256
#define LL 256
#define B_ITER 16   // batches per thread; tables stay in registers

// Scratch tables (no allocation allowed in kernel_launch).
__device__ float g_sx[BB * MM];   // 0.5*sin(x)
__device__ float g_cx[BB * MM];   // 0.5*cos(x)
__device__ float g_sp[MM * LL];   // sin(phi)
__device__ float g_cp[MM * LL];   // cos(phi)

__global__ void prep_sincos_kernel(const float* __restrict__ x,
                                   const float* __restrict__ phis) {
    int i = blockIdx.x * blockDim.x + threadIdx.x;
    if (i < BB * MM) {
        float s, c;
        sincosf(x[i], &s, &c);
        g_sx[i] = 0.5f * s;      // fold the 0.5 scale here
        g_cx[i] = 0.5f * c;
    }
    if (i < MM * LL) {
        float s, c;
        sincosf(phis[i], &s, &c);
        g_sp[i] = s;
        g_cp[i] = c;
    }
}

__device__ __forceinline__ float elem(float xv, float sx2, float cx2,
                                      float iv, float niv,
                                      float phv, float cpv, float spv) {
    float diff = xv - phv;                    // identical fp32 op to reference
    bool mask = (diff > niv) & (diff <= iv);  // exact reference semantics
    // val = 0.5*cos(x-phi)+0.5 = cp*(0.5*cx) + sp*(0.5*sx) + 0.5
    float val = fmaf(cpv, cx2, fmaf(spv, sx2, 0.5f));
    return mask ? val : 0.0f;
}

// Each thread owns one (m, l4) slot: loads phi/cos/sin for its 4 l-values ONCE,
// then iterates over B_ITER batches, writing one coalesced float4 per batch.
// gridDim.x = 64 (covers 16384 ml4 slots with 256-thread blocks)
// gridDim.y = BB / B_ITER = 64 (batch chunks)
__global__ void __launch_bounds__(256)
bcos_main_kernel(const float* __restrict__ x,
                 const float* __restrict__ phis,
                 const float* __restrict__ interval,
                 float4* __restrict__ out) {
    int ml4 = blockIdx.x * 256 + threadIdx.x;   // 0..16383
    int m   = ml4 >> 6;                         // 64 float4 per m-row
    int b0  = blockIdx.y * B_ITER;

    float iv  = __ldg(interval + m);
    float niv = -iv;

    float4 ph = reinterpret_cast<const float4*>(phis)[ml4];
    float4 cp = reinterpret_cast<const float4*>(g_cp)[ml4];
    float4 sp = reinterpret_cast<const float4*>(g_sp)[ml4];

    const float* xp  = x    + b0 * MM + m;
    const float* sxp = g_sx + b0 * MM + m;
    const float* cxp = g_cx + b0 * MM + m;
    float4* op = out + (size_t)b0 * (MM * LL / 4) + ml4;

#pragma unroll 4
    for (int i = 0; i < B_ITER; i++) {
        float xv  = __ldg(xp);   xp  += MM;
        float sx2 = *sxp;        sxp += MM;
        float cx2 = *cxp;        cxp += MM;

        float4 o;
        o.x = elem(xv, sx2, cx2, iv, niv, ph.x, cp.x, sp.x);
        o.y = elem(xv, sx2, cx2, iv, niv, ph.y, cp.y, sp.y);
        o.z = elem(xv, sx2, cx2, iv, niv, ph.z, cp.z, sp.z);
        o.w = elem(xv, sx2, cx2, iv, niv, ph.w, cp.w, sp.w);

        __stcs(op, o);           // streaming store: don't pollute L2
        op += MM * LL / 4;
    }
}

extern "C" void kernel_launch(void* const* d_in, const int* in_sizes, int n_in,
                              void* d_out, int out_size) {
    const float* x        = (const float*)d_in[0];  // (1024, 256)
    const float* phis     = (const float*)d_in[1];  // (256, 256)
    const float* interval = (const float*)d_in[2];  // (256,)
    float4* out = (float4*)d_out;                   // (1024, 65536) fp32

    prep_sincos_kernel<<<(BB * MM + 255) / 256, 256>>>(x, phis);

    dim3 grid(MM * LL / 4 / 256, BB / B_ITER);      // (64, 64)
    bcos_main_kernel<<<grid, 256>>>(x, phis, interval, out);
}

// round 5
// speedup vs baseline: 1.6131x; 1.0180x over previous
#include <cuda_runtime.h>
#include <cuda_bf16.h>

// Problem shape (fixed by the reference setup_inputs)
#define BB 1024
#define MM 256
#define LL 256
#define B_ITER 8    // batches per thread; grid = 8192 CTAs -> 6.92 waves @ 8 CTA/SM

// Scratch tables (no allocation allowed in kernel_launch).
__device__ float2 g_scx[BB * MM];  // {0.5*sin(x), 0.5*cos(x)}
__device__ float  g_sp[MM * LL];   // sin(phi)
__device__ float  g_cp[MM * LL];   // cos(phi)

__global__ void prep_sincos_kernel(const float* __restrict__ x,
                                   const float* __restrict__ phis) {
    int i = blockIdx.x * blockDim.x + threadIdx.x;
    if (i < BB * MM) {
        float s, c;
        sincosf(x[i], &s, &c);
        g_scx[i] = make_float2(0.5f * s, 0.5f * c);
    }
    if (i < MM * LL) {
        float s, c;
        sincosf(phis[i], &s, &c);
        g_sp[i] = s;
        g_cp[i] = c;
    }
}

__device__ __forceinline__ float elem(float xv, float sx2, float cx2,
                                      float iv, float niv,
                                      float phv, float cpv, float spv) {
    float diff = xv - phv;                    // identical fp32 op to reference
    bool mask = (diff > niv) & (diff <= iv);  // exact reference semantics
    // val = 0.5*cos(x-phi)+0.5 = cp*(0.5*cx) + sp*(0.5*sx) + 0.5
    float val = fmaf(cpv, cx2, fmaf(spv, sx2, 0.5f));
    return mask ? val : 0.0f;
}

// Each thread owns one (m, l4) slot: loads phi/cos/sin for its 4 l-values ONCE,
// then iterates over B_ITER batches, writing one coalesced float4 per batch.
// gridDim.x = 64 (16384 ml4 slots / 256 threads)
// gridDim.y = BB / B_ITER = 128 (batch chunks)
__global__ void __launch_bounds__(256)
bcos_main_kernel(const float* __restrict__ x,
                 const float* __restrict__ phis,
                 const float* __restrict__ interval,
                 float4* __restrict__ out) {
    int ml4 = blockIdx.x * 256 + threadIdx.x;   // 0..16383
    int m   = ml4 >> 6;                         // 64 float4 per m-row
    int b0  = blockIdx.y * B_ITER;

    float iv  = __ldg(interval + m);
    float niv = -iv;

    const float4* __restrict__ cp_tab = reinterpret_cast<const float4*>(g_cp);
    const float4* __restrict__ sp_tab = reinterpret_cast<const float4*>(g_sp);

    float4 ph = reinterpret_cast<const float4*>(phis)[ml4];
    float4 cp = cp_tab[ml4];
    float4 sp = sp_tab[ml4];

    const float*  __restrict__ xp   = x     + b0 * MM + m;
    const float2* __restrict__ scxp = g_scx + b0 * MM + m;
    float4* op = out + (size_t)b0 * (MM * LL / 4) + ml4;

#pragma unroll
    for (int i = 0; i < B_ITER; i++) {
        float  xv  = __ldg(xp);   xp   += MM;
        float2 scx = *scxp;       scxp += MM;

        float4 o;
        o.x = elem(xv, scx.x, scx.y, iv, niv, ph.x, cp.x, sp.x);
        o.y = elem(xv, scx.x, scx.y, iv, niv, ph.y, cp.y, sp.y);
        o.z = elem(xv, scx.x, scx.y, iv, niv, ph.z, cp.z, sp.z);
        o.w = elem(xv, scx.x, scx.y, iv, niv, ph.w, cp.w, sp.w);

        __stcs(op, o);           // streaming store: don't pollute L2
        op += MM * LL / 4;
    }
}

extern "C" void kernel_launch(void* const* d_in, const int* in_sizes, int n_in,
                              void* d_out, int out_size) {
    const float* x        = (const float*)d_in[0];  // (1024, 256)
    const float* phis     = (const float*)d_in[1];  // (256, 256)
    const float* interval = (const float*)d_in[2];  // (256,)
    float4* out = (float4*)d_out;                   // (1024, 65536) fp32

    prep_sincos_kernel<<<(BB * MM + 255) / 256, 256>>>(x, phis);

    dim3 grid(MM * LL / 4 / 256, BB / B_ITER);      // (64, 128) = 8192 CTAs
    bcos_main_kernel<<<grid, 256>>>(x, phis, interval, out);
}

// round 6
// speedup vs baseline: 1.6672x; 1.0335x over previous
#include <cuda_runtime.h>
#include <cuda_bf16.h>

// Problem shape (fixed by the reference setup_inputs)
#define BB 1024
#define MM 256
#define LL 256
#define B_ITER 8    // batches per CTA; grid = 8192 CTAs -> 6.92 waves @ 8 CTA/SM

// Scratch tables for phi only (no allocation allowed in kernel_launch).
__device__ float g_sp[MM * LL];   // sin(phi)
__device__ float g_cp[MM * LL];   // cos(phi)

// Prep: phi sincos only (65536 values). Fast: 256 blocks.
__global__ void prep_phi_kernel(const float* __restrict__ phis) {
    int i = blockIdx.x * blockDim.x + threadIdx.x;
    float s, c;
    sincosf(phis[i], &s, &c);
    g_sp[i] = s;
    g_cp[i] = c;
}

__device__ __forceinline__ float elem(float xv, float sx2, float cx2,
                                      float iv, float niv,
                                      float phv, float cpv, float spv) {
    float diff = xv - phv;                    // identical fp32 op to reference
    bool mask = (diff > niv) & (diff <= iv);  // exact reference semantics
    // val = 0.5*cos(x-phi)+0.5 = cp*(0.5*cx) + sp*(0.5*sx) + 0.5
    float val = fmaf(cpv, cx2, fmaf(spv, sx2, 0.5f));
    return mask ? val : 0.0f;
}

// Each CTA covers 4 m-rows (256 ml4 slots) x B_ITER batches.
// Prologue: threads 0..31 compute sincos(x[b][m]) for the CTA's 8x4 (b,m)
// pairs into smem (broadcast-read in the loop). Then the batch loop streams
// one coalesced float4 store per thread per iteration.
__global__ void __launch_bounds__(256)
bcos_main_kernel(const float* __restrict__ x,
                 const float* __restrict__ phis,
                 const float* __restrict__ interval,
                 float4* __restrict__ out) {
    __shared__ float2 s_scx[B_ITER * 4];   // {0.5*sin(x), 0.5*cos(x)} per (b,m)
    __shared__ float  s_x[B_ITER * 4];     // raw x for exact diff

    int tid = threadIdx.x;
    int ml4 = blockIdx.x * 256 + tid;      // 0..16383
    int m   = ml4 >> 6;                    // 64 float4 per m-row
    int b0  = blockIdx.y * B_ITER;
    int m_base = (blockIdx.x * 256) >> 6;  // first m of this CTA (4 per CTA)

    if (tid < B_ITER * 4) {
        int bi = tid >> 2;                 // 0..7
        int mi = tid & 3;                  // 0..3
        float xv = x[(b0 + bi) * MM + m_base + mi];
        float s, c;
        sincosf(xv, &s, &c);
        s_scx[tid] = make_float2(0.5f * s, 0.5f * c);
        s_x[tid]   = xv;
    }

    float iv  = __ldg(interval + m);
    float niv = -iv;

    float4 ph = reinterpret_cast<const float4*>(phis)[ml4];
    float4 cp = reinterpret_cast<const float4*>(g_cp)[ml4];
    float4 sp = reinterpret_cast<const float4*>(g_sp)[ml4];

    __syncthreads();

    int mi = m & 3;
    float4* op = out + (size_t)b0 * (MM * LL / 4) + ml4;

#pragma unroll
    for (int i = 0; i < B_ITER; i++) {
        int slot = (i << 2) | mi;
        float  xv  = s_x[slot];            // smem broadcast
        float2 scx = s_scx[slot];

        float4 o;
        o.x = elem(xv, scx.x, scx.y, iv, niv, ph.x, cp.x, sp.x);
        o.y = elem(xv, scx.x, scx.y, iv, niv, ph.y, cp.y, sp.y);
        o.z = elem(xv, scx.x, scx.y, iv, niv, ph.z, cp.z, sp.z);
        o.w = elem(xv, scx.x, scx.y, iv, niv, ph.w, cp.w, sp.w);

        __stcs(op, o);                     // streaming store: don't pollute L2
        op += MM * LL / 4;
    }
}

extern "C" void kernel_launch(void* const* d_in, const int* in_sizes, int n_in,
                              void* d_out, int out_size) {
    const float* x        = (const float*)d_in[0];  // (1024, 256)
    const float* phis     = (const float*)d_in[1];  // (256, 256)
    const float* interval = (const float*)d_in[2];  // (256,)
    float4* out = (float4*)d_out;                   // (1024, 65536) fp32

    prep_phi_kernel<<<MM * LL / 256, 256>>>(phis);

    dim3 grid(MM * LL / 4 / 256, BB / B_ITER);      // (64, 128) = 8192 CTAs
    bcos_main_kernel<<<grid, 256>>>(x, phis, interval, out);
}

// round 7
// speedup vs baseline: 1.7131x; 1.0275x over previous
#include <cuda_runtime.h>
#include <cuda_bf16.h>

// Problem shape (fixed by the reference setup_inputs)
#define BB 1024
#define MM 256
#define LL 256
#define B_ITER 8    // batches per CTA; grid = 8192 CTAs

__device__ __forceinline__ float elem(float xv, float sx2, float cx2,
                                      float iv, float niv,
                                      float phv, float cpv, float spv) {
    float diff = xv - phv;                    // identical fp32 op to reference
    bool mask = (diff > niv) & (diff <= iv);  // exact reference semantics
    // val = 0.5*cos(x-phi)+0.5 = cp*(0.5*cx) + sp*(0.5*sx) + 0.5
    float val = fmaf(cpv, cx2, fmaf(spv, sx2, 0.5f));
    return mask ? val : 0.0f;
}

// Single fused kernel. Each thread owns one (m, l4) slot (4 phi values, private
// sincos in prologue). Each warp is single-m (64 float4 slots per m-row), so
// the 8 x-sincos values the warp needs live in lanes 0..7 and are shuffle-
// broadcast per batch iteration. No smem, no barrier, no prep kernel.
__global__ void __launch_bounds__(256)
bcos_fused_kernel(const float* __restrict__ x,
                  const float* __restrict__ phis,
                  const float* __restrict__ interval,
                  float4* __restrict__ out) {
    int tid  = threadIdx.x;
    int ml4  = blockIdx.x * 256 + tid;     // 0..16383
    int m    = ml4 >> 6;                   // warp-uniform (64 slots per m)
    int b0   = blockIdx.y * B_ITER;
    int lane = tid & 31;

    // Lanes 0..7 hold x/sincos(x) for batches b0..b0+7 (lanes 8..31 redundant).
    float my_x = __ldg(x + (b0 + (lane & 7)) * MM + m);
    float s0, c0;
    sincosf(my_x, &s0, &c0);
    float my_s = 0.5f * s0;
    float my_c = 0.5f * c0;

    float iv  = __ldg(interval + m);
    float niv = -iv;

    float4 ph = reinterpret_cast<const float4*>(phis)[ml4];
    float spx, cpx, spy, cpy, spz, cpz, spw, cpw;
    sincosf(ph.x, &spx, &cpx);
    sincosf(ph.y, &spy, &cpy);
    sincosf(ph.z, &spz, &cpz);
    sincosf(ph.w, &spw, &cpw);

    float4* op = out + (size_t)b0 * (MM * LL / 4) + ml4;

#pragma unroll
    for (int i = 0; i < B_ITER; i++) {
        float xv = __shfl_sync(0xffffffffu, my_x, i);
        float s2 = __shfl_sync(0xffffffffu, my_s, i);
        float c2 = __shfl_sync(0xffffffffu, my_c, i);

        float4 o;
        o.x = elem(xv, s2, c2, iv, niv, ph.x, cpx, spx);
        o.y = elem(xv, s2, c2, iv, niv, ph.y, cpy, spy);
        o.z = elem(xv, s2, c2, iv, niv, ph.z, cpz, spz);
        o.w = elem(xv, s2, c2, iv, niv, ph.w, cpw, spw);

        __stcs(op, o);                     // streaming store: don't pollute L2
        op += MM * LL / 4;
    }
}

extern "C" void kernel_launch(void* const* d_in, const int* in_sizes, int n_in,
                              void* d_out, int out_size) {
    const float* x        = (const float*)d_in[0];  // (1024, 256)
    const float* phis     = (const float*)d_in[1];  // (256, 256)
    const float* interval = (const float*)d_in[2];  // (256,)
    float4* out = (float4*)d_out;                   // (1024, 65536) fp32

    dim3 grid(MM * LL / 4 / 256, BB / B_ITER);      // (64, 128) = 8192 CTAs
    bcos_fused_kernel<<<grid, 256>>>(x, phis, interval, out);
}